// round 8
// baseline (speedup 1.0000x reference)
#include <cuda_runtime.h>
#include <cstdint>

// FLoss: mean((1 - output[i, target[i]])^2)
// output: f32 [N,2]; target: int32 [N]. HBM-bound: 192 MiB in, 4 B out.
// cp.async (LDGSTS) per-thread pipeline: load destinations live in SMEM, not
// registers, so in-flight memory is smem-bound (~37 KB/CTA staged) instead of
// register-bound (~6 KB/SM). 3 stages, no barriers in the main loop.

#define NBLOCKS 1776           // 12 per SM = 2 waves at 6 resident CTAs (smem-bound)
#define NTHREADS 256
#define NSTAGES 3

__device__ float        g_partials[NBLOCKS];
__device__ unsigned int g_done_count = 0;  // atomicInc wraps to 0 -> replay-safe

__device__ __forceinline__ float quad_term(float4 v0, float4 v1, int4 t) {
    float a = (t.x == 0) ? v0.x : v0.y;
    float b = (t.y == 0) ? v0.z : v0.w;
    float c = (t.z == 0) ? v1.x : v1.y;
    float d = (t.w == 0) ? v1.z : v1.w;
    float da = 1.0f - a, db = 1.0f - b, dc = 1.0f - c, dd = 1.0f - d;
    return fmaf(da, da, db * db) + fmaf(dc, dc, dd * dd);
}

__device__ __forceinline__ float block_reduce(float acc, float* warp_sums) {
    #pragma unroll
    for (int off = 16; off > 0; off >>= 1)
        acc += __shfl_xor_sync(0xFFFFFFFFu, acc, off);
    int lane = threadIdx.x & 31;
    int wid  = threadIdx.x >> 5;
    if (lane == 0) warp_sums[wid] = acc;
    __syncthreads();
    float v = 0.0f;
    if (wid == 0) {
        v = (lane < NTHREADS / 32) ? warp_sums[lane] : 0.0f;
        #pragma unroll
        for (int off = 4; off > 0; off >>= 1)
            v += __shfl_xor_sync(0xFFFFFFFFu, v, off);
    }
    return v;  // valid in warp 0 lane 0
}

__global__ __launch_bounds__(NTHREADS)
void floss_cpasync_kernel(const float* __restrict__ out,
                          const int* __restrict__ tgt,
                          int nq /* = N/4 */,
                          float inv_n,
                          float* __restrict__ d_out) {
    // Per stage: 2*NTHREADS float4 (out rows) + NTHREADS int4 (targets) = 12 KiB.
    __shared__ alignas(16) float4 s_out[NSTAGES][2 * NTHREADS];
    __shared__ alignas(16) int4   s_tgt[NSTAGES][NTHREADS];
    __shared__ float warp_sums[NTHREADS / 32];

    const float4* outv = reinterpret_cast<const float4*>(out);
    const int4*   tgtv = reinterpret_cast<const int4*>(tgt);

    const int t  = threadIdx.x;
    const int j0 = blockIdx.x * NTHREADS + t;
    const int stride = NBLOCKS * NTHREADS;

    // Units (4 rows each) this thread processes.
    const int iters = (j0 < nq) ? (1 + (nq - 1 - j0) / stride) : 0;

    const uint32_t so0 = (uint32_t)__cvta_generic_to_shared(&s_out[0][t]);
    const uint32_t so1 = (uint32_t)__cvta_generic_to_shared(&s_out[0][t + NTHREADS]);
    const uint32_t st0 = (uint32_t)__cvta_generic_to_shared(&s_tgt[0][t]);
    const uint32_t OUT_STAGE = (uint32_t)(sizeof(float4) * 2 * NTHREADS);  // 8192
    const uint32_t TGT_STAGE = (uint32_t)(sizeof(int4) * NTHREADS);        // 4096

    auto issue = [&](int i) {
        if (i < iters) {
            size_t u = (size_t)(j0 + i * stride);
            uint32_t s = (uint32_t)(i % NSTAGES);
            const float4* p0 = &outv[2 * u];
            const int4*   pt = &tgtv[u];
            asm volatile("cp.async.cg.shared.global [%0], [%1], 16;"
                         :: "r"(so0 + s * OUT_STAGE), "l"(p0));
            asm volatile("cp.async.cg.shared.global [%0], [%1], 16;"
                         :: "r"(so1 + s * OUT_STAGE), "l"(p0 + 1));
            asm volatile("cp.async.cg.shared.global [%0], [%1], 16;"
                         :: "r"(st0 + s * TGT_STAGE), "l"(pt));
        }
        // Commit every iteration (possibly empty) -> constant group cadence.
        asm volatile("cp.async.commit_group;" ::: "memory");
    };

    // Prologue: fill all NSTAGES stages (groups 0..NSTAGES-1).
    #pragma unroll
    for (int i = 0; i < NSTAGES; ++i) issue(i);

    float acc = 0.0f;
    for (int i = 0; i < iters; ++i) {
        // Committed so far: NSTAGES + i groups; allow NSTAGES-1 pending -> group i done.
        asm volatile("cp.async.wait_group %0;" :: "n"(NSTAGES - 1) : "memory");
        int s = i % NSTAGES;
        float4 v0 = s_out[s][t];
        float4 v1 = s_out[s][t + NTHREADS];
        int4   ta = s_tgt[s][t];
        issue(i + NSTAGES);  // refill the stage we just read
        acc += quad_term(v0, v1, ta);
    }
    asm volatile("cp.async.wait_all;" ::: "memory");

    float bsum = block_reduce(acc, warp_sums);

    __shared__ bool is_last;
    if (threadIdx.x == 0) {
        g_partials[blockIdx.x] = bsum;
        __threadfence();
        unsigned int prev = atomicInc(&g_done_count, NBLOCKS - 1);
        is_last = (prev == NBLOCKS - 1);
    }
    __syncthreads();

    if (is_last) {
        float facc = 0.0f;
        for (int i = threadIdx.x; i < NBLOCKS; i += NTHREADS)
            facc += g_partials[i];
        __syncthreads();  // warp_sums reuse safe
        float total = block_reduce(facc, warp_sums);
        if (threadIdx.x == 0) d_out[0] = total * inv_n;
    }
}

extern "C" void kernel_launch(void* const* d_in, const int* in_sizes, int n_in,
                              void* d_out, int out_size) {
    const float* output = (const float*)d_in[0];  // [N, 2] f32
    const int*   target = (const int*)d_in[1];    // [N] int32

    long long n = (long long)in_sizes[1];  // N
    int nq = (int)(n / 4);                 // groups of 4 rows

    floss_cpasync_kernel<<<NBLOCKS, NTHREADS>>>(output, target, nq,
                                                1.0f / (float)n, (float*)d_out);
}

// round 10
// speedup vs baseline: 1.6644x; 1.6644x over previous
#include <cuda_runtime.h>

// FLoss: mean((1 - output[i, target[i]])^2)
// output: f32 [N,2]; target: int32 [N]. HBM-bound: 192 MiB in, 4 B out.
// Fused kernel: grid-stride unroll-5 LDG.128 stream (best measured config:
// 1536 blocks; cp.async and single-wave variants measured slower).

#define NBLOCKS 1536
#define NTHREADS 256

__device__ float        g_partials[NBLOCKS];
__device__ unsigned int g_done_count = 0;  // atomicInc wraps to 0 -> replay-safe

__device__ __forceinline__ float quad_term(float4 v0, float4 v1, int4 t) {
    float a = (t.x == 0) ? v0.x : v0.y;
    float b = (t.y == 0) ? v0.z : v0.w;
    float c = (t.z == 0) ? v1.x : v1.y;
    float d = (t.w == 0) ? v1.z : v1.w;
    float da = 1.0f - a, db = 1.0f - b, dc = 1.0f - c, dd = 1.0f - d;
    return fmaf(da, da, db * db) + fmaf(dc, dc, dd * dd);
}

__device__ __forceinline__ float block_reduce(float acc, float* warp_sums) {
    #pragma unroll
    for (int off = 16; off > 0; off >>= 1)
        acc += __shfl_xor_sync(0xFFFFFFFFu, acc, off);
    int lane = threadIdx.x & 31;
    int wid  = threadIdx.x >> 5;
    if (lane == 0) warp_sums[wid] = acc;
    __syncthreads();
    float v = 0.0f;
    if (wid == 0) {
        v = (lane < NTHREADS / 32) ? warp_sums[lane] : 0.0f;
        #pragma unroll
        for (int off = 4; off > 0; off >>= 1)
            v += __shfl_xor_sync(0xFFFFFFFFu, v, off);
    }
    return v;  // valid in warp 0 lane 0
}

__global__ __launch_bounds__(NTHREADS)
void floss_fused_kernel(const float* __restrict__ out,
                        const int* __restrict__ tgt,
                        int nq /* = N/4 */,
                        float inv_n,
                        float* __restrict__ d_out) {
    const float4* outv = reinterpret_cast<const float4*>(out);  // 2 rows per float4
    const int4*   tgtv = reinterpret_cast<const int4*>(tgt);    // 4 targets per int4

    float acc = 0.0f;
    int j = blockIdx.x * NTHREADS + threadIdx.x;
    const int stride = NBLOCKS * NTHREADS;

    // Unroll-by-5: 15 independent streaming loads in flight per thread.
    // At N=16.7M / 1536x256: 10.67 units/thread -> 2 deep trips + <=1 remainder.
    for (; j + 4 * stride < nq; j += 5 * stride) {
        int j1 = j + stride, j2 = j + 2 * stride, j3 = j + 3 * stride,
            j4 = j + 4 * stride;
        float4 a0 = __ldcs(&outv[2 * j]);
        float4 a1 = __ldcs(&outv[2 * j + 1]);
        float4 b0 = __ldcs(&outv[2 * j1]);
        float4 b1 = __ldcs(&outv[2 * j1 + 1]);
        float4 c0 = __ldcs(&outv[2 * j2]);
        float4 c1 = __ldcs(&outv[2 * j2 + 1]);
        float4 d0 = __ldcs(&outv[2 * j3]);
        float4 d1 = __ldcs(&outv[2 * j3 + 1]);
        float4 e0 = __ldcs(&outv[2 * j4]);
        float4 e1 = __ldcs(&outv[2 * j4 + 1]);
        int4   ta = __ldcs(&tgtv[j]);
        int4   tb = __ldcs(&tgtv[j1]);
        int4   tc = __ldcs(&tgtv[j2]);
        int4   td = __ldcs(&tgtv[j3]);
        int4   te = __ldcs(&tgtv[j4]);
        acc += quad_term(a0, a1, ta);
        acc += quad_term(b0, b1, tb);
        acc += quad_term(c0, c1, tc);
        acc += quad_term(d0, d1, td);
        acc += quad_term(e0, e1, te);
    }
    // Remainder (<=1 unit per thread at the benchmark shape)
    for (; j < nq; j += stride) {
        float4 a0 = __ldcs(&outv[2 * j]);
        float4 a1 = __ldcs(&outv[2 * j + 1]);
        int4   ta = __ldcs(&tgtv[j]);
        acc += quad_term(a0, a1, ta);
    }

    __shared__ float warp_sums[NTHREADS / 32];
    float bsum = block_reduce(acc, warp_sums);

    __shared__ bool is_last;
    if (threadIdx.x == 0) {
        g_partials[blockIdx.x] = bsum;
        __threadfence();
        unsigned int prev = atomicInc(&g_done_count, NBLOCKS - 1);
        is_last = (prev == NBLOCKS - 1);
    }
    __syncthreads();

    if (is_last) {
        float facc = 0.0f;
        for (int i = threadIdx.x; i < NBLOCKS; i += NTHREADS)
            facc += g_partials[i];
        __syncthreads();  // warp_sums reuse safe
        float total = block_reduce(facc, warp_sums);
        if (threadIdx.x == 0) d_out[0] = total * inv_n;
    }
}

extern "C" void kernel_launch(void* const* d_in, const int* in_sizes, int n_in,
                              void* d_out, int out_size) {
    const float* output = (const float*)d_in[0];  // [N, 2] f32
    const int*   target = (const int*)d_in[1];    // [N] int32

    long long n = (long long)in_sizes[1];  // N
    int nq = (int)(n / 4);                 // groups of 4 rows

    floss_fused_kernel<<<NBLOCKS, NTHREADS>>>(output, target, nq,
                                              1.0f / (float)n, (float*)d_out);
}